// round 2
// baseline (speedup 1.0000x reference)
#include <cuda_runtime.h>
#include <cstdint>

typedef unsigned long long u64;

#define N_MAX 65536
#define K_MAX 4096
#define D_MAX 256

// Scratch (allocation-free rule: __device__ globals)
__device__ float g_c2[K_MAX];
__device__ float g_segsum[K_MAX * D_MAX];
__device__ int   g_segcnt[K_MAX];
__device__ int   g_labels[N_MAX];
__device__ float g_minq[N_MAX];   // min over k of (c2[k] - 2*x.c[k])
__device__ float g_loss;

__device__ __forceinline__ u64 ffma2(u64 a, u64 b, u64 c) {
    u64 d;
    asm("fma.rn.f32x2 %0, %1, %2, %3;" : "=l"(d) : "l"(a), "l"(b), "l"(c));
    return d;
}

// ---------------------------------------------------------------------------
__global__ void init_kernel(int KD, int K) {
    int i = blockIdx.x * blockDim.x + threadIdx.x;
    if (i < KD) g_segsum[i] = 0.0f;
    if (i < K)  g_segcnt[i] = 0;
    if (i == 0) g_loss = 0.0f;
}

// ---------------------------------------------------------------------------
__global__ void c2_kernel(const float* __restrict__ C, int D) {
    int k = blockIdx.x;
    int t = threadIdx.x;
    float s = 0.0f;
    for (int d = t * 4; d < D; d += blockDim.x * 4) {
        float4 v = *(const float4*)(C + (size_t)k * D + d);
        s += v.x * v.x + v.y * v.y + v.z * v.z + v.w * v.w;
    }
    #pragma unroll
    for (int o = 16; o; o >>= 1) s += __shfl_down_sync(0xffffffffu, s, o);
    __shared__ float ws[2];
    if ((t & 31) == 0) ws[t >> 5] = s;
    __syncthreads();
    if (t == 0) g_c2[k] = ws[0] + ws[1];
}

// ---------------------------------------------------------------------------
// Assign kernel: fused SGEMM + argmin, now using packed f32x2 FFMA2.
// Block = 256 threads (16x16), tile = 128 rows x 128 centers, D-chunk = 16.
// Accumulators packed along the row axis: acc2[i2][j] = (dot(row 2*i2, c_j),
//                                                        dot(row 2*i2+1, c_j)).
// a-pairs come free from contiguous As; B tile stored DUPLICATED in smem so
// LDS.128 yields two dup-pairs with zero pack instructions in the inner loop.
// ---------------------------------------------------------------------------
#define BM 128
#define BK 128
#define DC 16
#define SPAD 4

__global__ __launch_bounds__(256) void assign_kernel(
    const float* __restrict__ X, const float* __restrict__ C,
    int N, int K, int D)
{
    __shared__ float As [DC][BM + SPAD];          // rows (transposed)
    __shared__ float Bsd[DC][2 * BK + SPAD];      // centers, duplicated: b,b,b',b',...

    int tid = threadIdx.x;
    int tx = tid & 15;          // center direction (8 cols each)
    int ty = tid >> 4;          // row direction (8 rows each)
    int rowBase = blockIdx.x * BM;

    float minv[8];
    int   mini[8];
    #pragma unroll
    for (int i = 0; i < 8; i++) { minv[i] = 3.0e38f; mini[i] = 0; }

    for (int k0 = 0; k0 < K; k0 += BK) {
        u64 acc2[4][8];
        #pragma unroll
        for (int i2 = 0; i2 < 4; i2++)
            #pragma unroll
            for (int j = 0; j < 8; j++) acc2[i2][j] = 0ull;

        for (int d0 = 0; d0 < D; d0 += DC) {
            #pragma unroll
            for (int p = 0; p < 2; p++) {
                int f4 = tid + p * 256;        // 0..511
                int m  = f4 >> 2;              // 0..127
                int q  = (f4 & 3) << 2;        // 0,4,8,12
                float4 va = *(const float4*)(X + (size_t)(rowBase + m) * D + d0 + q);
                float4 vb = *(const float4*)(C + (size_t)(k0 + m) * D + d0 + q);
                As[q + 0][m] = va.x; As[q + 1][m] = va.y;
                As[q + 2][m] = va.z; As[q + 3][m] = va.w;
                *(float2*)&Bsd[q + 0][2 * m] = make_float2(vb.x, vb.x);
                *(float2*)&Bsd[q + 1][2 * m] = make_float2(vb.y, vb.y);
                *(float2*)&Bsd[q + 2][2 * m] = make_float2(vb.z, vb.z);
                *(float2*)&Bsd[q + 3][2 * m] = make_float2(vb.w, vb.w);
            }
            __syncthreads();

            #pragma unroll
            for (int dc = 0; dc < DC; dc++) {
                u64 a2[4], b2[8];
                {
                    ulonglong2 t0 = *(const ulonglong2*)&As[dc][ty * 8];
                    ulonglong2 t1 = *(const ulonglong2*)&As[dc][ty * 8 + 4];
                    a2[0] = t0.x; a2[1] = t0.y; a2[2] = t1.x; a2[3] = t1.y;
                }
                {
                    ulonglong2 t0 = *(const ulonglong2*)&Bsd[dc][tx * 16];
                    ulonglong2 t1 = *(const ulonglong2*)&Bsd[dc][tx * 16 + 4];
                    ulonglong2 t2 = *(const ulonglong2*)&Bsd[dc][tx * 16 + 8];
                    ulonglong2 t3 = *(const ulonglong2*)&Bsd[dc][tx * 16 + 12];
                    b2[0] = t0.x; b2[1] = t0.y; b2[2] = t1.x; b2[3] = t1.y;
                    b2[4] = t2.x; b2[5] = t2.y; b2[6] = t3.x; b2[7] = t3.y;
                }
                #pragma unroll
                for (int i2 = 0; i2 < 4; i2++)
                    #pragma unroll
                    for (int j = 0; j < 8; j++)
                        acc2[i2][j] = ffma2(a2[i2], b2[j], acc2[i2][j]);
            }
            __syncthreads();
        }

        // Fold this 128-center tile into the running argmin of (c2 - 2*dot).
        #pragma unroll
        for (int j = 0; j < 8; j++) {
            int col = k0 + tx * 8 + j;
            float c2 = __ldg(&g_c2[col]);
            #pragma unroll
            for (int i2 = 0; i2 < 4; i2++) {
                float dlo = __uint_as_float((unsigned)(acc2[i2][j] & 0xffffffffull));
                float dhi = __uint_as_float((unsigned)(acc2[i2][j] >> 32));
                float qlo = fmaf(-2.0f, dlo, c2);
                float qhi = fmaf(-2.0f, dhi, c2);
                int ilo = 2 * i2, ihi = 2 * i2 + 1;
                if (qlo < minv[ilo]) { minv[ilo] = qlo; mini[ilo] = col; }
                if (qhi < minv[ihi]) { minv[ihi] = qhi; mini[ihi] = col; }
            }
        }
    }

    // Cross-thread argmin reduce over the 16 tx lanes sharing each row.
    #pragma unroll
    for (int s = 1; s < 16; s <<= 1) {
        #pragma unroll
        for (int i = 0; i < 8; i++) {
            float ov = __shfl_xor_sync(0xffffffffu, minv[i], s);
            int   oi = __shfl_xor_sync(0xffffffffu, mini[i], s);
            if (ov < minv[i] || (ov == minv[i] && oi < mini[i])) {
                minv[i] = ov; mini[i] = oi;
            }
        }
    }

    if (tx == 0) {
        #pragma unroll
        for (int i = 0; i < 8; i++) {
            int row = rowBase + ty * 8 + i;
            g_labels[row] = mini[i];
            g_minq[row]   = minv[i];
        }
    }
}

// ---------------------------------------------------------------------------
__global__ __launch_bounds__(256) void scatter_kernel(
    const float* __restrict__ X, float* __restrict__ out_labels, int D)
{
    int r    = blockIdx.x * 4 + (threadIdx.x >> 6);
    int lane = threadIdx.x & 63;
    int lab  = g_labels[r];

    float4 v = *(const float4*)(X + (size_t)r * D + lane * 4);
    float* dst = g_segsum + (size_t)lab * D + lane * 4;
    atomicAdd(dst + 0, v.x);
    atomicAdd(dst + 1, v.y);
    atomicAdd(dst + 2, v.z);
    atomicAdd(dst + 3, v.w);

    float part = v.x * v.x + v.y * v.y + v.z * v.z + v.w * v.w;
    if (lane == 0) {
        part += g_minq[r];                 // x2 + (c2 - 2 x.c) = d2_min
        atomicAdd(&g_segcnt[lab], 1);
        out_labels[r] = (float)lab;
    }

    #pragma unroll
    for (int o = 16; o; o >>= 1) part += __shfl_down_sync(0xffffffffu, part, o);
    __shared__ float ws[8];
    if ((threadIdx.x & 31) == 0) ws[threadIdx.x >> 5] = part;
    __syncthreads();
    if (threadIdx.x < 8) {
        float s = ws[threadIdx.x];
        #pragma unroll
        for (int o = 4; o; o >>= 1) s += __shfl_down_sync(0xffu, s, o);
        if (threadIdx.x == 0) atomicAdd(&g_loss, s);
    }
}

// ---------------------------------------------------------------------------
__global__ void finalize_kernel(
    const float* __restrict__ centers, const int* __restrict__ counts,
    float* __restrict__ out_centers, float* __restrict__ out_counts,
    float* __restrict__ out_loss, int K, int D, float invN)
{
    int idx = blockIdx.x * blockDim.x + threadIdx.x;
    if (idx < K * D) {
        int k = idx / D;
        float c0  = (float)counts[k];
        float cnt = (float)g_segcnt[k];
        out_centers[idx] = (c0 * centers[idx] + g_segsum[idx]) / (c0 + cnt);
    }
    if (idx < K) out_counts[idx] = (float)(counts[idx] + g_segcnt[idx]);
    if (idx == 0) out_loss[0] = g_loss * invN;
}

// ---------------------------------------------------------------------------
extern "C" void kernel_launch(void* const* d_in, const int* in_sizes, int n_in,
                              void* d_out, int out_size)
{
    const float* X      = (const float*)d_in[0];   // embedded [N,D]
    const float* C      = (const float*)d_in[1];   // centers  [K,D]
    const int*   counts = (const int*)  d_in[2];   // counts   [K]

    int K = in_sizes[2];
    int D = in_sizes[1] / K;
    int N = in_sizes[0] / D;
    int KD = K * D;

    float* out         = (float*)d_out;
    float* out_labels  = out;                       // [N]
    float* out_centers = out + N;                   // [K*D]
    float* out_counts  = out + N + (size_t)KD;      // [K]
    float* out_loss    = out_counts + K;            // [1]

    init_kernel<<<(KD + 255) / 256, 256>>>(KD, K);
    c2_kernel<<<K, 64>>>(C, D);
    assign_kernel<<<N / BM, 256>>>(X, C, N, K, D);
    scatter_kernel<<<N / 4, 256>>>(X, out_labels, D);
    finalize_kernel<<<(KD + 255) / 256, 256>>>(C, counts, out_centers, out_counts,
                                               out_loss, K, D, 1.0f / (float)N);
}

// round 4
// speedup vs baseline: 3.2055x; 3.2055x over previous
#include <cuda_runtime.h>
#include <cstdint>

// ------------------------- fixed problem shape -----------------------------
#define NROWS 65536
#define KCENT 4096
#define DIM   256

// ------------------------- device scratch ----------------------------------
__device__ float g_c2[KCENT];
__device__ float g_segsum[KCENT * DIM];
__device__ int   g_segcnt[KCENT];
__device__ int   g_labels[NROWS];
__device__ float g_minq[NROWS];
__device__ float g_loss;
// tf32 split, fragment-ready layout: [row][512 u32 words]
// word = chunk*64 + kb*16 + p*4 + wb + {0:hi,1:lo}, k = chunk*32+kb*8+p(+4 if wb=2)
__device__ uint32_t g_xf[(size_t)NROWS * 512];   // 128 MB
__device__ uint32_t g_cf[(size_t)KCENT * 512];   // 8 MB

// ------------------------- helpers ------------------------------------------
__device__ __forceinline__ uint32_t f2tf32(float v) {
    uint32_t r;
    asm("cvt.rna.tf32.f32 %0, %1;" : "=r"(r) : "f"(v));
    return r;
}

__device__ __forceinline__ void mma1688(float* d,
    uint32_t a0, uint32_t a1, uint32_t a2, uint32_t a3,
    uint32_t b0, uint32_t b1)
{
    asm volatile(
        "mma.sync.aligned.m16n8k8.row.col.f32.tf32.tf32.f32 "
        "{%0,%1,%2,%3}, {%4,%5,%6,%7}, {%8,%9}, {%0,%1,%2,%3};"
        : "+f"(d[0]), "+f"(d[1]), "+f"(d[2]), "+f"(d[3])
        : "r"(a0), "r"(a1), "r"(a2), "r"(a3), "r"(b0), "r"(b1));
}

// ---------------------------------------------------------------------------
__global__ void init_kernel(int KD, int K) {
    int i = blockIdx.x * blockDim.x + threadIdx.x;
    if (i < KD) g_segsum[i] = 0.0f;
    if (i < K)  g_segcnt[i] = 0;
    if (i == 0) g_loss = 0.0f;
}

__global__ void c2_kernel(const float* __restrict__ C, int D) {
    int k = blockIdx.x;
    int t = threadIdx.x;
    float s = 0.0f;
    for (int d = t * 4; d < D; d += blockDim.x * 4) {
        float4 v = *(const float4*)(C + (size_t)k * D + d);
        s += v.x * v.x + v.y * v.y + v.z * v.z + v.w * v.w;
    }
    #pragma unroll
    for (int o = 16; o; o >>= 1) s += __shfl_down_sync(0xffffffffu, s, o);
    __shared__ float ws[2];
    if ((t & 31) == 0) ws[t >> 5] = s;
    __syncthreads();
    if (t == 0) g_c2[k] = ws[0] + ws[1];
}

// fp32 -> (tf32 hi, tf32 lo), written to the fragment-ready layout.
__global__ void split_tf32_kernel(const float* __restrict__ src,
                                  uint32_t* __restrict__ dst, int rows) {
    int t = blockIdx.x * blockDim.x + threadIdx.x;
    if (t >= rows * 64) return;
    int row = t >> 6;
    int k4  = (t & 63) * 4;
    float4 v = *(const float4*)(src + (size_t)row * DIM + k4);
    int c  = k4 >> 5;
    int kk = k4 & 31;
    int kb = kk >> 3;
    int wb = (kk & 4) >> 1;
    uint32_t* base = dst + (size_t)row * 512 + c * 64 + kb * 16 + wb;
    float e[4] = {v.x, v.y, v.z, v.w};
    #pragma unroll
    for (int j = 0; j < 4; j++) {
        uint32_t h = f2tf32(e[j]);
        uint32_t l = f2tf32(e[j] - __uint_as_float(h));
        uint2 hl = make_uint2(h, l);
        *(uint2*)(base + j * 4) = hl;
    }
}

// ---------------------------------------------------------------------------
// Assign: fused 3xTF32 mma.sync GEMM + argmin.
// CTA: 256 threads (8 warps), 128 rows x full 4096 centers (32 tiles of 128).
// Warp tile 32 rows x 64 cols; chunk kc=32; per k8: 12 LDS.128 + 48 HMMA.
// ---------------------------------------------------------------------------
#define SM_A_U4   0                     // 128 rows * 20 uint4
#define SM_B_U4   2560
#define SM_C2_U32 20480                 // u32 offsets from here
#define SM_REDV   20608
#define SM_REDI   20864
#define SM_TOTAL_BYTES (21120 * 4)

__global__ __launch_bounds__(256, 2) void assign_mma_kernel() {
    extern __shared__ uint32_t sm[];
    uint4* As4 = (uint4*)sm;            // [r*20 + i]
    uint4* Bs4 = (uint4*)sm + SM_B_U4;
    float* c2s = (float*)(sm + SM_C2_U32);
    float* redv = (float*)(sm + SM_REDV);
    int*   redi = (int*)(sm + SM_REDI);

    int tid  = threadIdx.x;
    int lane = tid & 31;
    int wid  = tid >> 5;
    int wm   = wid & 3;            // warp row group (x32)
    int wn   = wid >> 2;           // warp col half (x64)
    int g    = lane >> 2;
    int t4   = lane & 3;
    int rsub = lane >> 4;
    int u    = lane & 15;
    int rowBase = blockIdx.x * 128;

    const uint4* xf = (const uint4*)g_xf;   // [row][128]
    const uint4* cf = (const uint4*)g_cf;

    float minv[4];
    int   mini[4];
    #pragma unroll
    for (int s = 0; s < 4; s++) { minv[s] = 3.0e38f; mini[s] = 0; }

    for (int nt0 = 0; nt0 < 32; nt0++) {
        __syncthreads();                       // epilogue of prev tile done
        if (tid < 128) c2s[tid] = g_c2[nt0 * 128 + tid];
        int nBase = nt0 * 128;

        float acc[2][8][4];
        #pragma unroll
        for (int mt = 0; mt < 2; mt++)
            #pragma unroll
            for (int nt = 0; nt < 8; nt++)
                #pragma unroll
                for (int j = 0; j < 4; j++) acc[mt][nt][j] = 0.0f;

        for (int c = 0; c < 8; c++) {
            __syncthreads();                   // prev chunk compute done
            #pragma unroll
            for (int s = 0; s < 8; s++) {
                int r = s * 16 + wid * 2 + rsub;
                As4[r * 20 + u] = xf[(size_t)(rowBase + r) * 128 + c * 16 + u];
                Bs4[r * 20 + u] = cf[(size_t)(nBase + r)  * 128 + c * 16 + u];
            }
            __syncthreads();

            #pragma unroll
            for (int kb = 0; kb < 4; kb++) {
                uint4 qa0[2], qa1[2];
                #pragma unroll
                for (int mt = 0; mt < 2; mt++) {
                    int rb = wm * 32 + mt * 16 + g;
                    qa0[mt] = As4[rb * 20 + kb * 4 + t4];        // row g
                    qa1[mt] = As4[(rb + 8) * 20 + kb * 4 + t4];  // row g+8
                }
                #pragma unroll
                for (int nt = 0; nt < 8; nt++) {
                    int n = wn * 64 + nt * 8 + g;
                    uint4 qb = Bs4[n * 20 + kb * 4 + t4];        // {b0h,b0l,b1h,b1l}
                    #pragma unroll
                    for (int mt = 0; mt < 2; mt++) {
                        // hi*hi
                        mma1688(acc[mt][nt], qa0[mt].x, qa1[mt].x, qa0[mt].z, qa1[mt].z,
                                qb.x, qb.z);
                        // hi*lo
                        mma1688(acc[mt][nt], qa0[mt].x, qa1[mt].x, qa0[mt].z, qa1[mt].z,
                                qb.y, qb.w);
                        // lo*hi
                        mma1688(acc[mt][nt], qa0[mt].y, qa1[mt].y, qa0[mt].w, qa1[mt].w,
                                qb.x, qb.z);
                    }
                }
            }
        }

        // Fold this 128-center tile into running argmin of (c2 - 2*dot).
        #pragma unroll
        for (int nt = 0; nt < 8; nt++) {
            int lc = wn * 64 + nt * 8 + 2 * t4;
            float c2a = c2s[lc], c2b = c2s[lc + 1];
            int col = nBase + lc;
            #pragma unroll
            for (int mt = 0; mt < 2; mt++) {
                float q0 = fmaf(-2.0f, acc[mt][nt][0], c2a);
                float q1 = fmaf(-2.0f, acc[mt][nt][1], c2b);
                float q2 = fmaf(-2.0f, acc[mt][nt][2], c2a);
                float q3 = fmaf(-2.0f, acc[mt][nt][3], c2b);
                int s0 = mt * 2, s1 = mt * 2 + 1;
                if (q0 < minv[s0]) { minv[s0] = q0; mini[s0] = col; }
                if (q1 < minv[s0]) { minv[s0] = q1; mini[s0] = col + 1; }
                if (q2 < minv[s1]) { minv[s1] = q2; mini[s1] = col; }
                if (q3 < minv[s1]) { minv[s1] = q3; mini[s1] = col + 1; }
            }
        }
    }

    // Reduce across the 4 t4 lanes sharing each row.
    #pragma unroll
    for (int s = 1; s <= 2; s <<= 1) {
        #pragma unroll
        for (int sl = 0; sl < 4; sl++) {
            float ov = __shfl_xor_sync(0xffffffffu, minv[sl], s);
            int   oi = __shfl_xor_sync(0xffffffffu, mini[sl], s);
            if (ov < minv[sl] || (ov == minv[sl] && oi < mini[sl])) {
                minv[sl] = ov; mini[sl] = oi;
            }
        }
    }
    if (t4 == 0) {
        #pragma unroll
        for (int sl = 0; sl < 4; sl++) {
            int rl = wm * 32 + (sl >> 1) * 16 + (sl & 1) * 8 + g;
            redv[rl * 2 + wn] = minv[sl];
            redi[rl * 2 + wn] = mini[sl];
        }
    }
    __syncthreads();
    if (tid < 128) {
        float v0 = redv[tid * 2], v1 = redv[tid * 2 + 1];
        int   i0 = redi[tid * 2], i1 = redi[tid * 2 + 1];
        float v; int i;
        if (v1 < v0 || (v1 == v0 && i1 < i0)) { v = v1; i = i1; }
        else                                  { v = v0; i = i0; }
        g_labels[rowBase + tid] = i;
        g_minq[rowBase + tid]   = v;
    }
}

// ---------------------------------------------------------------------------
__global__ __launch_bounds__(256) void scatter_kernel(
    const float* __restrict__ X, float* __restrict__ out_labels, int D)
{
    int r    = blockIdx.x * 4 + (threadIdx.x >> 6);
    int lane = threadIdx.x & 63;
    int lab  = g_labels[r];

    float4 v = *(const float4*)(X + (size_t)r * D + lane * 4);
    float* dst = g_segsum + (size_t)lab * D + lane * 4;
    atomicAdd(dst + 0, v.x);
    atomicAdd(dst + 1, v.y);
    atomicAdd(dst + 2, v.z);
    atomicAdd(dst + 3, v.w);

    float part = v.x * v.x + v.y * v.y + v.z * v.z + v.w * v.w;
    if (lane == 0) {
        part += g_minq[r];
        atomicAdd(&g_segcnt[lab], 1);
        out_labels[r] = (float)lab;
    }

    #pragma unroll
    for (int o = 16; o; o >>= 1) part += __shfl_down_sync(0xffffffffu, part, o);
    __shared__ float ws[8];
    if ((threadIdx.x & 31) == 0) ws[threadIdx.x >> 5] = part;
    __syncthreads();
    if (threadIdx.x < 8) {
        float s = ws[threadIdx.x];
        #pragma unroll
        for (int o = 4; o; o >>= 1) s += __shfl_down_sync(0xffu, s, o);
        if (threadIdx.x == 0) atomicAdd(&g_loss, s);
    }
}

// ---------------------------------------------------------------------------
__global__ void finalize_kernel(
    const float* __restrict__ centers, const int* __restrict__ counts,
    float* __restrict__ out_centers, float* __restrict__ out_counts,
    float* __restrict__ out_loss, int K, int D, float invN)
{
    int idx = blockIdx.x * blockDim.x + threadIdx.x;
    if (idx < K * D) {
        int k = idx / D;
        float c0  = (float)counts[k];
        float cnt = (float)g_segcnt[k];
        out_centers[idx] = (c0 * centers[idx] + g_segsum[idx]) / (c0 + cnt);
    }
    if (idx < K) out_counts[idx] = (float)(counts[idx] + g_segcnt[idx]);
    if (idx == 0) out_loss[0] = g_loss * invN;
}

// ---------------------------------------------------------------------------
extern "C" void kernel_launch(void* const* d_in, const int* in_sizes, int n_in,
                              void* d_out, int out_size)
{
    const float* X      = (const float*)d_in[0];
    const float* C      = (const float*)d_in[1];
    const int*   counts = (const int*)  d_in[2];

    const int N = NROWS, K = KCENT, D = DIM;
    const int KD = K * D;

    float* out         = (float*)d_out;
    float* out_labels  = out;
    float* out_centers = out + N;
    float* out_counts  = out + N + (size_t)KD;
    float* out_loss    = out_counts + K;

    static uint32_t* xf_ptr = nullptr;
    static uint32_t* cf_ptr = nullptr;
    static bool configured = false;
    if (!configured) {
        cudaGetSymbolAddress((void**)&xf_ptr, g_xf);
        cudaGetSymbolAddress((void**)&cf_ptr, g_cf);
        cudaFuncSetAttribute(assign_mma_kernel,
                             cudaFuncAttributeMaxDynamicSharedMemorySize,
                             SM_TOTAL_BYTES);
        configured = true;
    }

    init_kernel<<<(KD + 255) / 256, 256>>>(KD, K);
    c2_kernel<<<K, 64>>>(C, D);
    split_tf32_kernel<<<(N * 64 + 255) / 256, 256>>>(X, xf_ptr, N);
    split_tf32_kernel<<<(K * 64 + 255) / 256, 256>>>(C, cf_ptr, K);
    assign_mma_kernel<<<N / 128, 256, SM_TOTAL_BYTES>>>();
    scatter_kernel<<<N / 4, 256>>>(X, out_labels, D);
    finalize_kernel<<<(KD + 255) / 256, 256>>>(C, counts, out_centers, out_counts,
                                               out_loss, K, D, 1.0f / (float)N);
}

// round 5
// speedup vs baseline: 6.7240x; 2.0977x over previous
#include <cuda_runtime.h>
#include <cuda_fp16.h>
#include <cstdint>

#define NROWS 65536
#define KCENT 4096
#define DIM   256

// ------------------------- device scratch ----------------------------------
__device__ float g_c2[KCENT];
__device__ float g_segsum[KCENT * DIM];
__device__ int   g_segcnt[KCENT];
__device__ int   g_labels[NROWS];
__device__ float g_minq[NROWS];
__device__ float g_loss;
// fp16 split, fragment-ready layout: [row][8 chunks][32 u32 words]
// chunk = 32 dims = 2 k16-blocks; block image (16 words):
//   w[4t+0]=h(2t,2t+1) w[4t+1]=h(2t+8,2t+9) w[4t+2]=m(2t,2t+1) w[4t+3]=m(2t+8,2t+9)
// block placed at offset ((row&1)*16) ^ (blk*16) within the chunk (parity stagger).
__device__ uint32_t g_xf2[(size_t)NROWS * 256];   // 64 MB
__device__ uint32_t g_cf2[(size_t)KCENT * 256];   // 4 MB

// ------------------------- helpers ------------------------------------------
__device__ __forceinline__ uint32_t smem_u32(const void* p) {
    uint32_t a;
    asm("{ .reg .u64 t; cvta.to.shared.u64 t, %1; cvt.u32.u64 %0, t; }" : "=r"(a) : "l"(p));
    return a;
}

__device__ __forceinline__ void mma16816(float* d,
    uint32_t a0, uint32_t a1, uint32_t a2, uint32_t a3, uint32_t b0, uint32_t b1)
{
    asm volatile(
        "mma.sync.aligned.m16n8k16.row.col.f32.f16.f16.f32 "
        "{%0,%1,%2,%3}, {%4,%5,%6,%7}, {%8,%9}, {%0,%1,%2,%3};"
        : "+f"(d[0]), "+f"(d[1]), "+f"(d[2]), "+f"(d[3])
        : "r"(a0), "r"(a1), "r"(a2), "r"(a3), "r"(b0), "r"(b1));
}

__device__ __forceinline__ uint4 lds128(uint32_t byte_addr) {
    uint4 v;
    asm volatile("ld.shared.v4.u32 {%0,%1,%2,%3}, [%4];"
        : "=r"(v.x), "=r"(v.y), "=r"(v.z), "=r"(v.w) : "r"(byte_addr));
    return v;
}

__device__ __forceinline__ void cp16(uint32_t smem_byte, const void* gptr) {
    asm volatile("cp.async.cg.shared.global [%0], [%1], 16;" :: "r"(smem_byte), "l"(gptr));
}
#define CP_COMMIT() asm volatile("cp.async.commit_group;" ::: "memory")
#define CP_WAIT(n)  asm volatile("cp.async.wait_group %0;" :: "n"(n) : "memory")

__device__ __forceinline__ uint32_t packh(float a, float b) {
    __half2 p = __halves2half2(__float2half_rn(a), __float2half_rn(b));
    return *(uint32_t*)&p;
}

// ---------------------------------------------------------------------------
__global__ void init_kernel(int KD, int K) {
    int i = blockIdx.x * blockDim.x + threadIdx.x;
    if (i < KD) g_segsum[i] = 0.0f;
    if (i < K)  g_segcnt[i] = 0;
    if (i == 0) g_loss = 0.0f;
}

__global__ void c2_kernel(const float* __restrict__ C, int D) {
    int k = blockIdx.x;
    int t = threadIdx.x;
    float s = 0.0f;
    for (int d = t * 4; d < D; d += blockDim.x * 4) {
        float4 v = *(const float4*)(C + (size_t)k * D + d);
        s += v.x * v.x + v.y * v.y + v.z * v.z + v.w * v.w;
    }
    #pragma unroll
    for (int o = 16; o; o >>= 1) s += __shfl_down_sync(0xffffffffu, s, o);
    __shared__ float ws[2];
    if ((t & 31) == 0) ws[t >> 5] = s;
    __syncthreads();
    if (t == 0) g_c2[k] = ws[0] + ws[1];
}

// fp32 -> fp16 (h, m*2048) fragment-ready layout. One thread per (row, k16-block).
__global__ void split_f16_kernel(const float* __restrict__ src,
                                 uint32_t* __restrict__ dst, int rows) {
    int t = blockIdx.x * blockDim.x + threadIdx.x;
    if (t >= rows * 16) return;
    int row = t >> 4;
    int b16 = t & 15;
    int c   = b16 >> 1;
    int blk = b16 & 1;
    const float* s = src + (size_t)row * DIM + c * 32 + blk * 16;
    float x[16];
    #pragma unroll
    for (int i = 0; i < 4; i++) *(float4*)(x + i * 4) = *(const float4*)(s + i * 4);
    float h[16], m[16];
    #pragma unroll
    for (int i = 0; i < 16; i++) {
        h[i] = __half2float(__float2half_rn(x[i]));
        m[i] = (x[i] - h[i]) * 2048.0f;
    }
    uint32_t w[16];
    #pragma unroll
    for (int q = 0; q < 4; q++) {
        w[4 * q + 0] = packh(h[2 * q],     h[2 * q + 1]);
        w[4 * q + 1] = packh(h[2 * q + 8], h[2 * q + 9]);
        w[4 * q + 2] = packh(m[2 * q],     m[2 * q + 1]);
        w[4 * q + 3] = packh(m[2 * q + 8], m[2 * q + 9]);
    }
    uint32_t* d = dst + (size_t)row * 256 + c * 32 + (((row & 1) << 4) ^ (blk << 4));
    #pragma unroll
    for (int i = 0; i < 4; i++) *(uint4*)(d + i * 4) = *(uint4*)(w + i * 4);
}

// ---------------------------------------------------------------------------
// Assign: fp16 split GEMM + argmin. A (128 rows x 1KB) resident in smem,
// B double-buffered kc=64 chunks via cp.async. 8 warps, warp tile 32x64.
// ---------------------------------------------------------------------------
#define A_WORDS 32768            // 128 KB
#define B_WORDS 8192             // 32 KB per buffer
#define SM_TOTAL_BYTES ((A_WORDS + 2 * B_WORDS) * 4 + 2048)

__global__ __launch_bounds__(256, 1) void assign_mma_kernel() {
    extern __shared__ uint32_t sm[];
    uint32_t* As = sm;
    uint32_t* Bs = sm + A_WORDS;
    float* redv = (float*)(sm + A_WORDS + 2 * B_WORDS);
    int*   redi = (int*)(redv + 256);

    int tid  = threadIdx.x;
    int lane = tid & 31;
    int wid  = tid >> 5;
    int wm   = wid & 3;
    int wn   = wid >> 2;
    int g    = lane >> 2;
    int t4   = lane & 3;
    int rowBase = blockIdx.x * 128;

    uint32_t sbA = smem_u32(As);
    uint32_t sbB = smem_u32(Bs);
    const uint4* xf = (const uint4*)g_xf2;   // row = 64 uint4
    const uint4* cf = (const uint4*)g_cf2;

    // ---- B chunk copy (chunk q covers tile q>>2, k-range (q&3)*64..+63) ----
    auto copy_chunk = [&](int q) {
        int nBase = (q >> 2) * 128;
        int j = q & 3;
        uint32_t dstb = sbB + (q & 1) * (B_WORDS * 4);
        #pragma unroll
        for (int i = 0; i < 8; i++) {
            int idx = tid + i * 256;              // 0..2047
            int r = idx >> 4, rem = idx & 15;
            cp16(dstb + idx * 16, cf + (size_t)(nBase + r) * 64 + j * 16 + rem);
        }
        CP_COMMIT();
    };

    copy_chunk(0);
    copy_chunk(1);

    // ---- A resident copy ----
    #pragma unroll 8
    for (int i = 0; i < 32; i++) {
        int idx = tid + i * 256;                  // 0..8191
        ((uint4*)As)[idx] = xf[(size_t)(rowBase + (idx >> 6)) * 64 + (idx & 63)];
    }

    float accA[2][8][4], accB[2][8][4];
    #pragma unroll
    for (int mt = 0; mt < 2; mt++)
        #pragma unroll
        for (int nt = 0; nt < 8; nt++)
            #pragma unroll
            for (int j = 0; j < 4; j++) { accA[mt][nt][j] = 0.0f; accB[mt][nt][j] = 0.0f; }

    float minv[4];
    int   mini[4];
    #pragma unroll
    for (int s = 0; s < 4; s++) { minv[s] = 3.0e38f; mini[s] = 0; }

    for (int q = 0; q < 128; q++) {
        if (q < 126) CP_WAIT(1); else CP_WAIT(0);
        __syncthreads();

        int j = q & 3;
        uint32_t bufb = sbB + (q & 1) * (B_WORDS * 4);

        #pragma unroll
        for (int kk = 0; kk < 4; kk++) {
            int s   = j * 4 + kk;        // global k16-step 0..15
            int gc  = s >> 1, ksa = s & 1;
            int cc  = kk >> 1, ks  = kk & 1;

            uint4 qa[2][2];
            #pragma unroll
            for (int mt = 0; mt < 2; mt++)
                #pragma unroll
                for (int rh = 0; rh < 2; rh++) {
                    int r = wm * 32 + mt * 16 + g + rh * 8;
                    uint32_t w = r * 256 + gc * 32 + (((r & 1) << 4) ^ (ksa << 4)) + t4 * 4;
                    qa[mt][rh] = lds128(sbA + w * 4);
                }

            #pragma unroll
            for (int nt = 0; nt < 8; nt++) {
                int n = wn * 64 + nt * 8 + g;
                uint32_t w = n * 64 + (cc << 5) + (((n & 1) << 4) ^ (ks << 4)) + t4 * 4;
                uint4 qb = lds128(bufb + w * 4);
                #pragma unroll
                for (int mt = 0; mt < 2; mt++) {
                    mma16816(accA[mt][nt], qa[mt][0].x, qa[mt][1].x, qa[mt][0].y, qa[mt][1].y, qb.x, qb.y); // hh
                    mma16816(accB[mt][nt], qa[mt][0].x, qa[mt][1].x, qa[mt][0].y, qa[mt][1].y, qb.z, qb.w); // h*m
                    mma16816(accB[mt][nt], qa[mt][0].z, qa[mt][1].z, qa[mt][0].w, qa[mt][1].w, qb.x, qb.y); // m*h
                }
            }
        }

        if ((q & 3) == 3) {
            int nBase = (q >> 2) * 128;
            #pragma unroll
            for (int nt = 0; nt < 8; nt++) {
                int lc = wn * 64 + nt * 8 + 2 * t4;
                float c2a = __ldg(&g_c2[nBase + lc]);
                float c2b = __ldg(&g_c2[nBase + lc + 1]);
                int col = nBase + lc;
                #pragma unroll
                for (int mt = 0; mt < 2; mt++) {
                    float d0 = fmaf(accB[mt][nt][0], 4.8828125e-4f, accA[mt][nt][0]);
                    float d1 = fmaf(accB[mt][nt][1], 4.8828125e-4f, accA[mt][nt][1]);
                    float d2 = fmaf(accB[mt][nt][2], 4.8828125e-4f, accA[mt][nt][2]);
                    float d3 = fmaf(accB[mt][nt][3], 4.8828125e-4f, accA[mt][nt][3]);
                    float q0 = fmaf(-2.0f, d0, c2a);
                    float q1 = fmaf(-2.0f, d1, c2b);
                    float q2 = fmaf(-2.0f, d2, c2a);
                    float q3 = fmaf(-2.0f, d3, c2b);
                    int s0 = mt * 2, s1 = mt * 2 + 1;
                    if (q0 < minv[s0]) { minv[s0] = q0; mini[s0] = col; }
                    if (q1 < minv[s0]) { minv[s0] = q1; mini[s0] = col + 1; }
                    if (q2 < minv[s1]) { minv[s1] = q2; mini[s1] = col; }
                    if (q3 < minv[s1]) { minv[s1] = q3; mini[s1] = col + 1; }
                    accA[mt][nt][0] = 0.0f; accA[mt][nt][1] = 0.0f;
                    accA[mt][nt][2] = 0.0f; accA[mt][nt][3] = 0.0f;
                    accB[mt][nt][0] = 0.0f; accB[mt][nt][1] = 0.0f;
                    accB[mt][nt][2] = 0.0f; accB[mt][nt][3] = 0.0f;
                }
            }
        }
        __syncthreads();
        if (q < 126) copy_chunk(q + 2);
    }

    // ---- argmin reduce across t4 lanes, then across the two wn halves ----
    #pragma unroll
    for (int s = 1; s <= 2; s <<= 1) {
        #pragma unroll
        for (int sl = 0; sl < 4; sl++) {
            float ov = __shfl_xor_sync(0xffffffffu, minv[sl], s);
            int   oi = __shfl_xor_sync(0xffffffffu, mini[sl], s);
            if (ov < minv[sl] || (ov == minv[sl] && oi < mini[sl])) {
                minv[sl] = ov; mini[sl] = oi;
            }
        }
    }
    if (t4 == 0) {
        #pragma unroll
        for (int sl = 0; sl < 4; sl++) {
            int rl = wm * 32 + (sl >> 1) * 16 + (sl & 1) * 8 + g;
            redv[rl * 2 + wn] = minv[sl];
            redi[rl * 2 + wn] = mini[sl];
        }
    }
    __syncthreads();
    if (tid < 128) {
        float v0 = redv[tid * 2], v1 = redv[tid * 2 + 1];
        int   i0 = redi[tid * 2], i1 = redi[tid * 2 + 1];
        float v; int i;
        if (v1 < v0 || (v1 == v0 && i1 < i0)) { v = v1; i = i1; }
        else                                  { v = v0; i = i0; }
        g_labels[rowBase + tid] = i;
        g_minq[rowBase + tid]   = v;
    }
}

// ---------------------------------------------------------------------------
__global__ __launch_bounds__(256) void scatter_kernel(
    const float* __restrict__ X, float* __restrict__ out_labels, int D)
{
    int r    = blockIdx.x * 4 + (threadIdx.x >> 6);
    int lane = threadIdx.x & 63;
    int lab  = g_labels[r];

    float4 v = *(const float4*)(X + (size_t)r * D + lane * 4);
    float* dst = g_segsum + (size_t)lab * D + lane * 4;
    atomicAdd(dst + 0, v.x);
    atomicAdd(dst + 1, v.y);
    atomicAdd(dst + 2, v.z);
    atomicAdd(dst + 3, v.w);

    float part = v.x * v.x + v.y * v.y + v.z * v.z + v.w * v.w;
    if (lane == 0) {
        part += g_minq[r];
        atomicAdd(&g_segcnt[lab], 1);
        out_labels[r] = (float)lab;
    }

    #pragma unroll
    for (int o = 16; o; o >>= 1) part += __shfl_down_sync(0xffffffffu, part, o);
    __shared__ float ws[8];
    if ((threadIdx.x & 31) == 0) ws[threadIdx.x >> 5] = part;
    __syncthreads();
    if (threadIdx.x < 8) {
        float s = ws[threadIdx.x];
        #pragma unroll
        for (int o = 4; o; o >>= 1) s += __shfl_down_sync(0xffu, s, o);
        if (threadIdx.x == 0) atomicAdd(&g_loss, s);
    }
}

// ---------------------------------------------------------------------------
__global__ void finalize_kernel(
    const float* __restrict__ centers, const int* __restrict__ counts,
    float* __restrict__ out_centers, float* __restrict__ out_counts,
    float* __restrict__ out_loss, int K, int D, float invN)
{
    int idx = blockIdx.x * blockDim.x + threadIdx.x;
    if (idx < K * D) {
        int k = idx / D;
        float c0  = (float)counts[k];
        float cnt = (float)g_segcnt[k];
        out_centers[idx] = (c0 * centers[idx] + g_segsum[idx]) / (c0 + cnt);
    }
    if (idx < K) out_counts[idx] = (float)(counts[idx] + g_segcnt[idx]);
    if (idx == 0) out_loss[0] = g_loss * invN;
}

// ---------------------------------------------------------------------------
extern "C" void kernel_launch(void* const* d_in, const int* in_sizes, int n_in,
                              void* d_out, int out_size)
{
    const float* X      = (const float*)d_in[0];
    const float* C      = (const float*)d_in[1];
    const int*   counts = (const int*)  d_in[2];

    const int N = NROWS, K = KCENT, D = DIM;
    const int KD = K * D;

    float* out         = (float*)d_out;
    float* out_labels  = out;
    float* out_centers = out + N;
    float* out_counts  = out + N + (size_t)KD;
    float* out_loss    = out_counts + K;

    static uint32_t* xf_ptr = nullptr;
    static uint32_t* cf_ptr = nullptr;
    static bool configured = false;
    if (!configured) {
        cudaGetSymbolAddress((void**)&xf_ptr, g_xf2);
        cudaGetSymbolAddress((void**)&cf_ptr, g_cf2);
        cudaFuncSetAttribute(assign_mma_kernel,
                             cudaFuncAttributeMaxDynamicSharedMemorySize,
                             SM_TOTAL_BYTES);
        configured = true;
    }

    init_kernel<<<(KD + 255) / 256, 256>>>(KD, K);
    c2_kernel<<<K, 64>>>(C, D);
    split_f16_kernel<<<(N * 16 + 255) / 256, 256>>>(X, xf_ptr, N);
    split_f16_kernel<<<(K * 16 + 255) / 256, 256>>>(C, cf_ptr, K);
    assign_mma_kernel<<<N / 128, 256, SM_TOTAL_BYTES>>>();
    scatter_kernel<<<N / 4, 256>>>(X, out_labels, D);
    finalize_kernel<<<(KD + 255) / 256, 256>>>(C, counts, out_centers, out_counts,
                                               out_loss, K, D, 1.0f / (float)N);
}

// round 6
// speedup vs baseline: 8.1373x; 1.2102x over previous
#include <cuda_runtime.h>
#include <cuda_fp16.h>
#include <cstdint>

#define NROWS 65536
#define KCENT 4096
#define DIM   256

// ------------------------- device scratch ----------------------------------
__device__ float g_c2[KCENT];
__device__ float g_segsum[KCENT * DIM];
__device__ int   g_segcnt[KCENT];
__device__ int   g_labels[2 * NROWS];   // [half][row]
__device__ float g_minq[2 * NROWS];
__device__ float g_loss;
// fp16 split, fragment-ready layout: [row][8 chunks][32 u32 words]
__device__ uint32_t g_xf2[(size_t)NROWS * 256];   // 64 MB
__device__ uint32_t g_cf2[(size_t)KCENT * 256];   // 4 MB

// ------------------------- helpers ------------------------------------------
__device__ __forceinline__ uint32_t smem_u32(const void* p) {
    uint32_t a;
    asm("{ .reg .u64 t; cvta.to.shared.u64 t, %1; cvt.u32.u64 %0, t; }" : "=r"(a) : "l"(p));
    return a;
}

__device__ __forceinline__ void mma16816(float* d,
    uint32_t a0, uint32_t a1, uint32_t a2, uint32_t a3, uint32_t b0, uint32_t b1)
{
    asm volatile(
        "mma.sync.aligned.m16n8k16.row.col.f32.f16.f16.f32 "
        "{%0,%1,%2,%3}, {%4,%5,%6,%7}, {%8,%9}, {%0,%1,%2,%3};"
        : "+f"(d[0]), "+f"(d[1]), "+f"(d[2]), "+f"(d[3])
        : "r"(a0), "r"(a1), "r"(a2), "r"(a3), "r"(b0), "r"(b1));
}

__device__ __forceinline__ uint4 lds128(uint32_t byte_addr) {
    uint4 v;
    asm volatile("ld.shared.v4.u32 {%0,%1,%2,%3}, [%4];"
        : "=r"(v.x), "=r"(v.y), "=r"(v.z), "=r"(v.w) : "r"(byte_addr));
    return v;
}

__device__ __forceinline__ void cp16(uint32_t smem_byte, const void* gptr) {
    asm volatile("cp.async.cg.shared.global [%0], [%1], 16;" :: "r"(smem_byte), "l"(gptr));
}
#define CP_COMMIT() asm volatile("cp.async.commit_group;" ::: "memory")
#define CP_WAIT(n)  asm volatile("cp.async.wait_group %0;" :: "n"(n) : "memory")

__device__ __forceinline__ uint32_t packh(float a, float b) {
    __half2 p = __halves2half2(__float2half_rn(a), __float2half_rn(b));
    return *(uint32_t*)&p;
}

// ---------------------------------------------------------------------------
__global__ void init_kernel(int KD, int K) {
    int i = blockIdx.x * blockDim.x + threadIdx.x;
    if (i < KD) g_segsum[i] = 0.0f;
    if (i < K)  g_segcnt[i] = 0;
    if (i == 0) g_loss = 0.0f;
}

__global__ void c2_kernel(const float* __restrict__ C, int D) {
    int k = blockIdx.x;
    int t = threadIdx.x;
    float s = 0.0f;
    for (int d = t * 4; d < D; d += blockDim.x * 4) {
        float4 v = *(const float4*)(C + (size_t)k * D + d);
        s += v.x * v.x + v.y * v.y + v.z * v.z + v.w * v.w;
    }
    #pragma unroll
    for (int o = 16; o; o >>= 1) s += __shfl_down_sync(0xffffffffu, s, o);
    __shared__ float ws[2];
    if ((t & 31) == 0) ws[t >> 5] = s;
    __syncthreads();
    if (t == 0) g_c2[k] = ws[0] + ws[1];
}

// fp32 -> fp16 (h, m*2048) fragment-ready layout. One thread per (row, k16-block).
__global__ void split_f16_kernel(const float* __restrict__ src,
                                 uint32_t* __restrict__ dst, int rows) {
    int t = blockIdx.x * blockDim.x + threadIdx.x;
    if (t >= rows * 16) return;
    int row = t >> 4;
    int b16 = t & 15;
    int c   = b16 >> 1;
    int blk = b16 & 1;
    const float* s = src + (size_t)row * DIM + c * 32 + blk * 16;
    float x[16];
    #pragma unroll
    for (int i = 0; i < 4; i++) *(float4*)(x + i * 4) = *(const float4*)(s + i * 4);
    float h[16], m[16];
    #pragma unroll
    for (int i = 0; i < 16; i++) {
        h[i] = __half2float(__float2half_rn(x[i]));
        m[i] = (x[i] - h[i]) * 2048.0f;
    }
    uint32_t w[16];
    #pragma unroll
    for (int q = 0; q < 4; q++) {
        w[4 * q + 0] = packh(h[2 * q],     h[2 * q + 1]);
        w[4 * q + 1] = packh(h[2 * q + 8], h[2 * q + 9]);
        w[4 * q + 2] = packh(m[2 * q],     m[2 * q + 1]);
        w[4 * q + 3] = packh(m[2 * q + 8], m[2 * q + 9]);
    }
    uint32_t* d = dst + (size_t)row * 256 + c * 32 + (((row & 1) << 4) ^ (blk << 4));
    #pragma unroll
    for (int i = 0; i < 4; i++) *(uint4*)(d + i * 4) = *(uint4*)(w + i * 4);
}

// ---------------------------------------------------------------------------
// Assign: fp16 split GEMM + argmin. 512 threads (16 warps), warp tile 32x32.
// Each CTA: 128 rows x 2048 centers (one column half). A resident (128 KB),
// B double-buffered kc=64 chunks via cp.async.
// ---------------------------------------------------------------------------
#define A_WORDS 32768            // 128 KB
#define B_WORDS 8192             // 32 KB per buffer
#define SM_TOTAL_BYTES ((A_WORDS + 2 * B_WORDS) * 4 + 4096)

__global__ __launch_bounds__(512, 1) void assign_mma_kernel() {
    extern __shared__ uint32_t sm[];
    uint32_t* As = sm;
    float* redv = (float*)(sm + A_WORDS + 2 * B_WORDS);
    int*   redi = (int*)(redv + 512);

    int tid  = threadIdx.x;
    int lane = tid & 31;
    int wid  = tid >> 5;
    int wm   = wid & 3;            // row group (x32)
    int wn   = wid >> 2;           // col group (x32), 0..3
    int g    = lane >> 2;
    int t4   = lane & 3;
    int colHalf = blockIdx.x & 1;
    int rowBase = (blockIdx.x >> 1) * 128;
    int colBase = colHalf * 2048;

    uint32_t sbA = smem_u32(As);
    uint32_t sbB = sbA + A_WORDS * 4;
    const uint4* xf = (const uint4*)g_xf2;   // row = 64 uint4
    const uint4* cf = (const uint4*)g_cf2;

    // ---- B chunk copy (chunk q covers tile q>>2 of this half, k-range (q&3)*64) ----
    auto copy_chunk = [&](int q) {
        int nBase = colBase + (q >> 2) * 128;
        int j = q & 3;
        uint32_t dstb = sbB + (q & 1) * (B_WORDS * 4);
        #pragma unroll
        for (int i = 0; i < 4; i++) {
            int idx = tid + i * 512;              // 0..2047
            int r = idx >> 4, rem = idx & 15;
            cp16(dstb + idx * 16, cf + (size_t)(nBase + r) * 64 + j * 16 + rem);
        }
        CP_COMMIT();
    };

    copy_chunk(0);
    copy_chunk(1);

    // ---- A resident copy ----
    #pragma unroll 4
    for (int i = 0; i < 16; i++) {
        int idx = tid + i * 512;                  // 0..8191
        ((uint4*)As)[idx] = xf[(size_t)(rowBase + (idx >> 6)) * 64 + (idx & 63)];
    }

    float accA[2][4][4], accB[2][4][4];
    #pragma unroll
    for (int mt = 0; mt < 2; mt++)
        #pragma unroll
        for (int nt = 0; nt < 4; nt++)
            #pragma unroll
            for (int j = 0; j < 4; j++) { accA[mt][nt][j] = 0.0f; accB[mt][nt][j] = 0.0f; }

    float minv[4];
    int   mini[4];
    #pragma unroll
    for (int s = 0; s < 4; s++) { minv[s] = 3.0e38f; mini[s] = 0; }

    for (int q = 0; q < 64; q++) {
        if (q < 62) CP_WAIT(1); else CP_WAIT(0);
        __syncthreads();

        int j = q & 3;
        uint32_t bufb = sbB + (q & 1) * (B_WORDS * 4);

        #pragma unroll
        for (int kk = 0; kk < 4; kk++) {
            int s   = j * 4 + kk;        // global k16-step 0..15
            int gc  = s >> 1, ksa = s & 1;
            int cc  = kk >> 1, ks  = kk & 1;

            uint4 qa[2][2];
            #pragma unroll
            for (int mt = 0; mt < 2; mt++)
                #pragma unroll
                for (int rh = 0; rh < 2; rh++) {
                    int r = wm * 32 + mt * 16 + g + rh * 8;
                    uint32_t w = r * 256 + gc * 32 + (((r & 1) << 4) ^ (ksa << 4)) + t4 * 4;
                    qa[mt][rh] = lds128(sbA + w * 4);
                }
            uint4 qb[4];
            #pragma unroll
            for (int nt = 0; nt < 4; nt++) {
                int n = wn * 32 + nt * 8 + g;
                uint32_t w = n * 64 + (cc << 5) + (((n & 1) << 4) ^ (ks << 4)) + t4 * 4;
                qb[nt] = lds128(bufb + w * 4);
            }

            // pass 1: hh -> accA
            #pragma unroll
            for (int nt = 0; nt < 4; nt++)
                #pragma unroll
                for (int mt = 0; mt < 2; mt++)
                    mma16816(accA[mt][nt], qa[mt][0].x, qa[mt][1].x, qa[mt][0].y, qa[mt][1].y,
                             qb[nt].x, qb[nt].y);
            // pass 2: h*m -> accB
            #pragma unroll
            for (int nt = 0; nt < 4; nt++)
                #pragma unroll
                for (int mt = 0; mt < 2; mt++)
                    mma16816(accB[mt][nt], qa[mt][0].x, qa[mt][1].x, qa[mt][0].y, qa[mt][1].y,
                             qb[nt].z, qb[nt].w);
            // pass 3: m*h -> accB
            #pragma unroll
            for (int nt = 0; nt < 4; nt++)
                #pragma unroll
                for (int mt = 0; mt < 2; mt++)
                    mma16816(accB[mt][nt], qa[mt][0].z, qa[mt][1].z, qa[mt][0].w, qa[mt][1].w,
                             qb[nt].x, qb[nt].y);
        }

        if ((q & 3) == 3) {
            int nBase = colBase + (q >> 2) * 128;
            #pragma unroll
            for (int nt = 0; nt < 4; nt++) {
                int lc = wn * 32 + nt * 8 + 2 * t4;
                float c2a = __ldg(&g_c2[nBase + lc]);
                float c2b = __ldg(&g_c2[nBase + lc + 1]);
                int col = nBase + lc;
                #pragma unroll
                for (int mt = 0; mt < 2; mt++) {
                    float d0 = fmaf(accB[mt][nt][0], 4.8828125e-4f, accA[mt][nt][0]);
                    float d1 = fmaf(accB[mt][nt][1], 4.8828125e-4f, accA[mt][nt][1]);
                    float d2 = fmaf(accB[mt][nt][2], 4.8828125e-4f, accA[mt][nt][2]);
                    float d3 = fmaf(accB[mt][nt][3], 4.8828125e-4f, accA[mt][nt][3]);
                    float q0 = fmaf(-2.0f, d0, c2a);
                    float q1 = fmaf(-2.0f, d1, c2b);
                    float q2 = fmaf(-2.0f, d2, c2a);
                    float q3 = fmaf(-2.0f, d3, c2b);
                    int s0 = mt * 2, s1 = mt * 2 + 1;
                    if (q0 < minv[s0]) { minv[s0] = q0; mini[s0] = col; }
                    if (q1 < minv[s0]) { minv[s0] = q1; mini[s0] = col + 1; }
                    if (q2 < minv[s1]) { minv[s1] = q2; mini[s1] = col; }
                    if (q3 < minv[s1]) { minv[s1] = q3; mini[s1] = col + 1; }
                    accA[mt][nt][0] = 0.0f; accA[mt][nt][1] = 0.0f;
                    accA[mt][nt][2] = 0.0f; accA[mt][nt][3] = 0.0f;
                    accB[mt][nt][0] = 0.0f; accB[mt][nt][1] = 0.0f;
                    accB[mt][nt][2] = 0.0f; accB[mt][nt][3] = 0.0f;
                }
            }
        }
        __syncthreads();
        if (q < 62) copy_chunk(q + 2);
    }

    // ---- argmin reduce across t4 lanes, then across the 4 wn groups ----
    #pragma unroll
    for (int s = 1; s <= 2; s <<= 1) {
        #pragma unroll
        for (int sl = 0; sl < 4; sl++) {
            float ov = __shfl_xor_sync(0xffffffffu, minv[sl], s);
            int   oi = __shfl_xor_sync(0xffffffffu, mini[sl], s);
            if (ov < minv[sl] || (ov == minv[sl] && oi < mini[sl])) {
                minv[sl] = ov; mini[sl] = oi;
            }
        }
    }
    if (t4 == 0) {
        #pragma unroll
        for (int sl = 0; sl < 4; sl++) {
            int rl = wm * 32 + (sl >> 1) * 16 + (sl & 1) * 8 + g;
            redv[rl * 4 + wn] = minv[sl];
            redi[rl * 4 + wn] = mini[sl];
        }
    }
    __syncthreads();
    if (tid < 128) {
        float v = redv[tid * 4];
        int   i = redi[tid * 4];
        #pragma unroll
        for (int c = 1; c < 4; c++) {
            float ov = redv[tid * 4 + c];
            int   oi = redi[tid * 4 + c];
            if (ov < v || (ov == v && oi < i)) { v = ov; i = oi; }
        }
        g_labels[colHalf * NROWS + rowBase + tid] = i;
        g_minq[colHalf * NROWS + rowBase + tid]   = v;
    }
}

// ---------------------------------------------------------------------------
// Scatter: combine the two column-half candidates, then seg_sum/cnt/loss.
// ---------------------------------------------------------------------------
__global__ __launch_bounds__(256) void scatter_kernel(
    const float* __restrict__ X, float* __restrict__ out_labels, int D)
{
    int r    = blockIdx.x * 4 + (threadIdx.x >> 6);
    int lane = threadIdx.x & 63;

    float v0 = g_minq[r],        v1 = g_minq[NROWS + r];
    int   l0 = g_labels[r],      l1 = g_labels[NROWS + r];
    int   lab;  float vmin;
    if (v1 < v0) { lab = l1; vmin = v1; } else { lab = l0; vmin = v0; }

    float4 v = *(const float4*)(X + (size_t)r * D + lane * 4);
    float* dst = g_segsum + (size_t)lab * D + lane * 4;
    atomicAdd(dst + 0, v.x);
    atomicAdd(dst + 1, v.y);
    atomicAdd(dst + 2, v.z);
    atomicAdd(dst + 3, v.w);

    float part = v.x * v.x + v.y * v.y + v.z * v.z + v.w * v.w;
    if (lane == 0) {
        part += vmin;
        atomicAdd(&g_segcnt[lab], 1);
        out_labels[r] = (float)lab;
    }

    #pragma unroll
    for (int o = 16; o; o >>= 1) part += __shfl_down_sync(0xffffffffu, part, o);
    __shared__ float ws[8];
    if ((threadIdx.x & 31) == 0) ws[threadIdx.x >> 5] = part;
    __syncthreads();
    if (threadIdx.x < 8) {
        float s = ws[threadIdx.x];
        #pragma unroll
        for (int o = 4; o; o >>= 1) s += __shfl_down_sync(0xffu, s, o);
        if (threadIdx.x == 0) atomicAdd(&g_loss, s);
    }
}

// ---------------------------------------------------------------------------
__global__ void finalize_kernel(
    const float* __restrict__ centers, const int* __restrict__ counts,
    float* __restrict__ out_centers, float* __restrict__ out_counts,
    float* __restrict__ out_loss, int K, int D, float invN)
{
    int idx = blockIdx.x * blockDim.x + threadIdx.x;
    if (idx < K * D) {
        int k = idx / D;
        float c0  = (float)counts[k];
        float cnt = (float)g_segcnt[k];
        out_centers[idx] = (c0 * centers[idx] + g_segsum[idx]) / (c0 + cnt);
    }
    if (idx < K) out_counts[idx] = (float)(counts[idx] + g_segcnt[idx]);
    if (idx == 0) out_loss[0] = g_loss * invN;
}

// ---------------------------------------------------------------------------
extern "C" void kernel_launch(void* const* d_in, const int* in_sizes, int n_in,
                              void* d_out, int out_size)
{
    const float* X      = (const float*)d_in[0];
    const float* C      = (const float*)d_in[1];
    const int*   counts = (const int*)  d_in[2];

    const int N = NROWS, K = KCENT, D = DIM;
    const int KD = K * D;

    float* out         = (float*)d_out;
    float* out_labels  = out;
    float* out_centers = out + N;
    float* out_counts  = out + N + (size_t)KD;
    float* out_loss    = out_counts + K;

    static uint32_t* xf_ptr = nullptr;
    static uint32_t* cf_ptr = nullptr;
    static bool configured = false;
    if (!configured) {
        cudaGetSymbolAddress((void**)&xf_ptr, g_xf2);
        cudaGetSymbolAddress((void**)&cf_ptr, g_cf2);
        cudaFuncSetAttribute(assign_mma_kernel,
                             cudaFuncAttributeMaxDynamicSharedMemorySize,
                             SM_TOTAL_BYTES);
        configured = true;
    }

    init_kernel<<<(KD + 255) / 256, 256>>>(KD, K);
    c2_kernel<<<K, 64>>>(C, D);
    split_f16_kernel<<<(N * 16 + 255) / 256, 256>>>(X, xf_ptr, N);
    split_f16_kernel<<<(K * 16 + 255) / 256, 256>>>(C, cf_ptr, K);
    assign_mma_kernel<<<2 * (N / 128), 512, SM_TOTAL_BYTES>>>();
    scatter_kernel<<<N / 4, 256>>>(X, out_labels, D);
    finalize_kernel<<<(KD + 255) / 256, 256>>>(C, counts, out_centers, out_counts,
                                               out_loss, K, D, 1.0f / (float)N);
}